// round 14
// baseline (speedup 1.0000x reference)
#include <cuda_runtime.h>
#include <cuda_bf16.h>
#include <cstdint>

#define N_NODES 50000
#define N_EDGES 800000
#define IN_DIM  128
#define OUT_DIM 64
#define CAP     64          // fixed bucket capacity per row (Poisson(16) tail @64 ~ 2e-18)

// ---------------------------------------------------------------------------
// static device scratch (no allocs allowed)
// ---------------------------------------------------------------------------
__device__ float g_hidden[N_NODES * OUT_DIM];     // 12.8 MB
__device__ int   g_pos[N_NODES];                  // fill cursor; ALWAYS zero between calls
__device__ int2  g_edge[N_NODES * CAP];           // 25.6 MB bucketed {col, val}

// ---------------------------------------------------------------------------
// helpers
// ---------------------------------------------------------------------------
__device__ __forceinline__ void cp_async16(uint32_t dst_smem, const void* src, int src_sz) {
    asm volatile("cp.async.cg.shared.global [%0], [%1], 16, %2;"
                 :: "r"(dst_smem), "l"(src), "r"(src_sz));
}
__device__ __forceinline__ void cp_async_commit_wait() {
    asm volatile("cp.async.commit_group;");
    asm volatile("cp.async.wait_group 0;" ::: "memory");
}
__device__ __forceinline__ uint32_t tf32_rna(float x) {
    uint32_t r;
    asm("cvt.rna.tf32.f32 %0, %1;" : "=r"(r) : "f"(x));
    return r;
}
// D += A * B  (m16n8k8, tf32 inputs, f32 accum)
__device__ __forceinline__ void mma_tf32(float* c, const uint32_t* a, uint32_t b0, uint32_t b1) {
    asm("mma.sync.aligned.m16n8k8.row.col.f32.tf32.tf32.f32 "
        "{%0,%1,%2,%3}, {%4,%5,%6,%7}, {%8,%9}, {%0,%1,%2,%3};"
        : "+f"(c[0]), "+f"(c[1]), "+f"(c[2]), "+f"(c[3])
        : "r"(a[0]), "r"(a[1]), "r"(a[2]), "r"(a[3]), "r"(b0), "r"(b1));
}

// ---------------------------------------------------------------------------
// Kernel 1 (MERGED): gemm blocks + fill blocks in one grid.
//   bid % 3 == 0 -> gemm block (gbid = bid/3, 782 of them)
//   else         -> fill block (fbid = bid - bid/3 - 1, 1563 of them)
// gemm and fill are independent (disjoint in/out); interleaving them per SM
// lets fill's memory traffic run inside gemm's latency stalls.
//
// gemm: 3xTF32 tensor-core GEMM (R12): 64 rows x 64 cols per block,
// 128 thr = 4 warps, K in 2 phases of 64, on-the-fly hi/lo splits.
// fill: 4 edges per thread into fixed 64-slot row buckets.
// NOTE: g_pos is NOT zeroed here — accum re-zeroes it after use, so it is
// always zero when this kernel starts (including the very first call: .bss).
// ---------------------------------------------------------------------------
#define MB 64                 // rows per gemm block
#define GEMM_THREADS 128
#define KP 64                 // k per phase
#define XSTR 68               // x smem row stride (floats)
#define WSTR 72               // w smem row stride (floats)
#define GEMM_BLOCKS ((N_NODES + MB - 1) / MB)            // 782
#define FILL_BLOCKS ((N_EDGES / 4 + GEMM_THREADS - 1) / GEMM_THREADS)  // 1563
#define MERGED_GRID (GEMM_BLOCKS + FILL_BLOCKS)          // 2345

__global__ void __launch_bounds__(GEMM_THREADS, 4)
gemm_fill_kernel(const float* __restrict__ x, const float* __restrict__ w,
                 const int* __restrict__ edge_row,
                 const int* __restrict__ edge_col,
                 const float* __restrict__ edge_val) {
    __shared__ float xs[MB * XSTR];     // 17.4 KB
    __shared__ float ws[KP * WSTR];     // 18.4 KB

    int bid = blockIdx.x;
    int tid = threadIdx.x;

    if (bid % 3 != 0) {
        // ---------------- fill path ----------------
        int fbid = bid - bid / 3 - 1;               // 0 .. FILL_BLOCKS-1
        int i = fbid * GEMM_THREADS + tid;          // group-of-4 index
        if (i < N_EDGES / 4) {
            int4   r4 = reinterpret_cast<const int4*>(edge_row)[i];
            int4   c4 = reinterpret_cast<const int4*>(edge_col)[i];
            float4 v4 = reinterpret_cast<const float4*>(edge_val)[i];

            int p;
            p = atomicAdd(&g_pos[r4.x], 1);
            if (p < CAP) g_edge[r4.x * CAP + p] = make_int2(c4.x, __float_as_int(v4.x));
            p = atomicAdd(&g_pos[r4.y], 1);
            if (p < CAP) g_edge[r4.y * CAP + p] = make_int2(c4.y, __float_as_int(v4.y));
            p = atomicAdd(&g_pos[r4.z], 1);
            if (p < CAP) g_edge[r4.z * CAP + p] = make_int2(c4.z, __float_as_int(v4.z));
            p = atomicAdd(&g_pos[r4.w], 1);
            if (p < CAP) g_edge[r4.w * CAP + p] = make_int2(c4.w, __float_as_int(v4.w));
        }
        return;
    }

    // ---------------- gemm path ----------------
    int gbid = bid / 3;
    int warp = tid >> 5;
    int lane = tid & 31;
    int g    = lane >> 2;               // group id (0..7)
    int t    = lane & 3;                // thread in group
    int bb   = gbid * MB;

    uint32_t xs_smem = (uint32_t)__cvta_generic_to_shared(xs);
    uint32_t ws_smem = (uint32_t)__cvta_generic_to_shared(ws);

    float acc[8][4];
    #pragma unroll
    for (int nt = 0; nt < 8; nt++)
        #pragma unroll
        for (int c = 0; c < 4; c++) acc[nt][c] = 0.f;

    const float4* x4 = reinterpret_cast<const float4*>(x);
    const float4* w4 = reinterpret_cast<const float4*>(w);
    const float* xr = xs + (warp * 16) * XSTR;   // this warp's 16 rows

    #pragma unroll
    for (int phase = 0; phase < 2; phase++) {
        if (phase > 0) __syncthreads();          // previous-phase compute done

        // ---- stage x[:, phase*64 .. +64): 64 rows x 16 chunks = 1024
        #pragma unroll
        for (int i = 0; i < (MB * KP / 4) / GEMM_THREADS; i++) {
            int c  = i * GEMM_THREADS + tid;
            int r  = c >> 4;
            int k4 = c & 15;
            int grow = bb + r;
            const float4* src = x4 + (size_t)grow * (IN_DIM / 4) + phase * (KP / 4) + k4;
            int sz = (grow < N_NODES) ? 16 : 0;
            const float4* safe = (grow < N_NODES) ? src : x4;
            cp_async16(xs_smem + (r * XSTR + k4 * 4) * 4, safe, sz);
        }
        // ---- stage w[phase*64 .. +64, :]: 64 k-rows x 16 chunks = 1024
        #pragma unroll
        for (int i = 0; i < (KP * OUT_DIM / 4) / GEMM_THREADS; i++) {
            int c  = i * GEMM_THREADS + tid;
            int r  = c >> 4;                     // k-row within phase
            int k4 = c & 15;
            cp_async16(ws_smem + (r * WSTR + k4 * 4) * 4,
                       w4 + (size_t)(phase * KP + r) * (OUT_DIM / 4) + k4, 16);
        }
        cp_async_commit_wait();
        __syncthreads();

        // ---- 8 k-steps of m16n8k8
        #pragma unroll
        for (int ks = 0; ks < KP / 8; ks++) {
            int kk = ks * 8;

            // A fragment (fp32 loads, then hi/lo tf32 split)
            float ar[4];
            ar[0] = xr[(g)     * XSTR + kk + t];
            ar[1] = xr[(g + 8) * XSTR + kk + t];
            ar[2] = xr[(g)     * XSTR + kk + t + 4];
            ar[3] = xr[(g + 8) * XSTR + kk + t + 4];
            uint32_t ah[4], al[4];
            #pragma unroll
            for (int i = 0; i < 4; i++) {
                ah[i] = tf32_rna(ar[i]);
                al[i] = tf32_rna(ar[i] - __uint_as_float(ah[i]));
            }

            #pragma unroll
            for (int nt = 0; nt < 8; nt++) {
                float br0 = ws[(kk + t)     * WSTR + nt * 8 + g];
                float br1 = ws[(kk + t + 4) * WSTR + nt * 8 + g];
                uint32_t bh0 = tf32_rna(br0);
                uint32_t bl0 = tf32_rna(br0 - __uint_as_float(bh0));
                uint32_t bh1 = tf32_rna(br1);
                uint32_t bl1 = tf32_rna(br1 - __uint_as_float(bh1));

                mma_tf32(acc[nt], ah, bh0, bh1);   // xh*wh
                mma_tf32(acc[nt], ah, bl0, bl1);   // xh*wl
                mma_tf32(acc[nt], al, bh0, bh1);   // xl*wh
            }
        }
    }

    // ---- epilogue: c0,c1 -> (row g, cols 2t,2t+1); c2,c3 -> (row g+8)
    int row0 = bb + warp * 16 + g;
    int row1 = row0 + 8;
    #pragma unroll
    for (int nt = 0; nt < 8; nt++) {
        int col = nt * 8 + 2 * t;
        if (row0 < N_NODES)
            *reinterpret_cast<float2*>(g_hidden + (size_t)row0 * OUT_DIM + col)
                = make_float2(acc[nt][0], acc[nt][1]);
        if (row1 < N_NODES)
            *reinterpret_cast<float2*>(g_hidden + (size_t)row1 * OUT_DIM + col)
                = make_float2(acc[nt][2], acc[nt][3]);
    }
}

// ---------------------------------------------------------------------------
// Kernel 2: fused accumulate + bias + relu.  One warp per node, lane owns
// 2 cols.  ALSO re-zeroes g_pos after reading it (store-after-read within
// the owning warp), so the next call starts with a clean cursor array.
// ---------------------------------------------------------------------------
__global__ void __launch_bounds__(256)
accum_kernel(float* __restrict__ out, const float* __restrict__ b) {
    int node = (blockIdx.x * blockDim.x + threadIdx.x) >> 5;
    int lane = threadIdx.x & 31;
    if (node >= N_NODES) return;

    int deg = g_pos[node];
    if (lane == 0) g_pos[node] = 0;          // reset cursor for next call
    deg = deg < CAP ? deg : CAP;
    int off = node * CAP;

    float accx = 0.f, accy = 0.f;
    const float* hbase = g_hidden + lane * 2;

    int base = 0;
    int full = deg & ~31;
    for (; base < full; base += 32) {
        int2 ev = g_edge[off + base + lane];
        #pragma unroll
        for (int j = 0; j < 32; j++) {
            int   col = __shfl_sync(0xffffffffu, ev.x, j);
            float val = __int_as_float(__shfl_sync(0xffffffffu, ev.y, j));
            float2 hv = *reinterpret_cast<const float2*>(hbase + (size_t)col * OUT_DIM);
            accx = fmaf(val, hv.x, accx);
            accy = fmaf(val, hv.y, accy);
        }
    }
    int rem = deg - base;
    if (rem > 0) {
        int2 ev = (lane < rem) ? g_edge[off + base + lane] : make_int2(0, 0);
        for (int j = 0; j < rem; j++) {
            int   col = __shfl_sync(0xffffffffu, ev.x, j);
            float val = __int_as_float(__shfl_sync(0xffffffffu, ev.y, j));
            float2 hv = *reinterpret_cast<const float2*>(hbase + (size_t)col * OUT_DIM);
            accx = fmaf(val, hv.x, accx);
            accy = fmaf(val, hv.y, accy);
        }
    }

    float2 bv = reinterpret_cast<const float2*>(b)[lane];
    accx = fmaxf(accx + bv.x, 0.f);
    accy = fmaxf(accy + bv.y, 0.f);
    *reinterpret_cast<float2*>(out + (size_t)node * OUT_DIM + lane * 2)
        = make_float2(accx, accy);
}

// ---------------------------------------------------------------------------
extern "C" void kernel_launch(void* const* d_in, const int* in_sizes, int n_in,
                              void* d_out, int out_size) {
    const float* x        = (const float*)d_in[0];
    const int*   edge_row = (const int*)  d_in[1];
    const int*   edge_col = (const int*)  d_in[2];
    const float* edge_val = (const float*)d_in[3];
    const float* w        = (const float*)d_in[4];
    const float* b        = (const float*)d_in[5];
    float* out = (float*)d_out;

    gemm_fill_kernel<<<MERGED_GRID, GEMM_THREADS>>>(x, w, edge_row, edge_col, edge_val);
    accum_kernel<<<(N_NODES * 32 + 255) / 256, 256>>>(out, b);
}

// round 16
// speedup vs baseline: 1.8618x; 1.8618x over previous
#include <cuda_runtime.h>
#include <cuda_bf16.h>
#include <cstdint>

#define N_NODES 50000
#define N_EDGES 800000
#define IN_DIM  128
#define OUT_DIM 64
#define CAP     64          // fixed bucket capacity per row (Poisson(16) tail @64 ~ 2e-18)

// ---------------------------------------------------------------------------
// static device scratch (no allocs allowed)
// ---------------------------------------------------------------------------
__device__ float g_hidden[N_NODES * OUT_DIM];     // 12.8 MB
__device__ int   g_pos[N_NODES];                  // fill cursor == degree after fill
__device__ int2  g_edge[N_NODES * CAP];           // 25.6 MB bucketed {col, val}

// per-lane pre-packed B fragments (tf32 hi/lo), [phase][ks][lane][20-word row]
#define PACK_STRIDE 20
__device__ __align__(16) uint32_t g_wpack_hi[512 * PACK_STRIDE];   // 40 KB
__device__ __align__(16) uint32_t g_wpack_lo[512 * PACK_STRIDE];   // 40 KB

// ---------------------------------------------------------------------------
// helpers
// ---------------------------------------------------------------------------
__device__ __forceinline__ void cp_async16(uint32_t dst_smem, const void* src, int src_sz) {
    asm volatile("cp.async.cg.shared.global [%0], [%1], 16, %2;"
                 :: "r"(dst_smem), "l"(src), "r"(src_sz));
}
__device__ __forceinline__ void cp_async_commit_wait() {
    asm volatile("cp.async.commit_group;");
    asm volatile("cp.async.wait_group 0;" ::: "memory");
}
__device__ __forceinline__ uint32_t tf32_rna(float x) {
    uint32_t r;
    asm("cvt.rna.tf32.f32 %0, %1;" : "=r"(r) : "f"(x));
    return r;
}
// D += A * B  (m16n8k8, tf32 inputs, f32 accum) — layout verified in R12
__device__ __forceinline__ void mma_tf32(float* c, const uint32_t* a, uint32_t b0, uint32_t b1) {
    asm("mma.sync.aligned.m16n8k8.row.col.f32.tf32.tf32.f32 "
        "{%0,%1,%2,%3}, {%4,%5,%6,%7}, {%8,%9}, {%0,%1,%2,%3};"
        : "+f"(c[0]), "+f"(c[1]), "+f"(c[2]), "+f"(c[3])
        : "r"(a[0]), "r"(a[1]), "r"(a[2]), "r"(a[3]), "r"(b0), "r"(b1));
}

// ---------------------------------------------------------------------------
// Kernel 0: pack w into per-lane tf32 hi/lo fragments (ONCE per launch).
// Row r = (phase<<8)|(ks<<5)|lane.  Word order: [2*nt]   = (k = kk+t,   n = nt*8+g)
//                                               [2*nt+1] = (k = kk+t+4, n = nt*8+g)
// — exactly the values lane (g,t) consumes in R12's verified fragment map.
// ---------------------------------------------------------------------------
__global__ void pack_kernel(const float* __restrict__ w) {
    int r = blockIdx.x * 256 + threadIdx.x;     // 0..511
    int lane = r & 31, ks = (r >> 5) & 7, phase = r >> 8;
    int g = lane >> 2, t = lane & 3;
    uint32_t base = (uint32_t)r * PACK_STRIDE;
    int k0 = phase * 64 + ks * 8 + t;
    #pragma unroll
    for (int nt = 0; nt < 8; nt++) {
        int n = nt * 8 + g;
        float f0 = w[k0 * OUT_DIM + n];
        float f1 = w[(k0 + 4) * OUT_DIM + n];
        uint32_t h0 = tf32_rna(f0), h1 = tf32_rna(f1);
        uint32_t l0 = tf32_rna(f0 - __uint_as_float(h0));
        uint32_t l1 = tf32_rna(f1 - __uint_as_float(h1));
        g_wpack_hi[base + 2 * nt]     = h0;
        g_wpack_hi[base + 2 * nt + 1] = h1;
        g_wpack_lo[base + 2 * nt]     = l0;
        g_wpack_lo[base + 2 * nt + 1] = l1;
    }
}

// ---------------------------------------------------------------------------
// Kernel 1: hidden = x @ w — 3xTF32 mma.sync GEMM with pre-packed B.
// Block = 64 rows x 64 cols, 128 threads = 4 warps; K in 2 phases of 64.
// Mainloop per k-step: A = 4 LDS + on-the-fly hi/lo split; B = 8x LDS.128
// from the per-lane pack (NO cvt/sub); 24 MMA.  D = xh*wh + xh*wl + xl*wh.
// Pack row stride 20 words -> LDS.128 bank positions {0,4,..,28}x4 lanes =
// optimal 4 phases per warp load.  smem 58.4 KB -> 3 blocks/SM.
// ALSO zeroes g_pos (kernel boundary orders it before fill).
// ---------------------------------------------------------------------------
#define MB 64
#define GEMM_THREADS 128
#define KP 64
#define XSTR 68                               // x smem row stride (floats)
#define XS_BYTES (MB * XSTR * 4)              // 17408
#define PACK_BYTES (256 * PACK_STRIDE * 4)    // 20480 per array per phase
#define SMEM_BH_OFF XS_BYTES
#define SMEM_BL_OFF (SMEM_BH_OFF + PACK_BYTES)
#define GEMM_SMEM_BYTES (SMEM_BL_OFF + PACK_BYTES)   // 58368
#define GEMM_GRID ((N_NODES + MB - 1) / MB)   // 782

__global__ void __launch_bounds__(GEMM_THREADS, 3)
gemm_kernel(const float* __restrict__ x) {
    extern __shared__ char smem[];
    float* xs = reinterpret_cast<float*>(smem);

    int tid  = threadIdx.x;
    int warp = tid >> 5;
    int lane = tid & 31;
    int g    = lane >> 2;
    int t    = lane & 3;
    int bb   = blockIdx.x * MB;

    uint32_t smem_u32 = (uint32_t)__cvta_generic_to_shared(smem);

    // fold in: zero g_pos (782*128 = 100096 >= 50000)
    {
        int gtid = blockIdx.x * GEMM_THREADS + tid;
        if (gtid < N_NODES) g_pos[gtid] = 0;
    }

    float acc[8][4];
    #pragma unroll
    for (int nt = 0; nt < 8; nt++)
        #pragma unroll
        for (int c = 0; c < 4; c++) acc[nt][c] = 0.f;

    const float4* x4 = reinterpret_cast<const float4*>(x);
    const float* xr = xs + (warp * 16) * XSTR;

    #pragma unroll
    for (int phase = 0; phase < 2; phase++) {
        if (phase > 0) __syncthreads();          // previous-phase compute done

        // ---- stage x[:, phase*64 .. +64): 64 rows x 16 chunks = 1024
        #pragma unroll
        for (int i = 0; i < (MB * KP / 4) / GEMM_THREADS; i++) {
            int c  = i * GEMM_THREADS + tid;
            int r  = c >> 4;
            int k4 = c & 15;
            int grow = bb + r;
            const float4* src = x4 + (size_t)grow * (IN_DIM / 4) + phase * (KP / 4) + k4;
            int sz = (grow < N_NODES) ? 16 : 0;
            const float4* safe = (grow < N_NODES) ? src : x4;
            cp_async16(smem_u32 + (r * XSTR + k4 * 4) * 4, safe, sz);
        }
        // ---- stage this phase's B pack (hi + lo): 1280 chunks each
        {
            const char* hsrc = reinterpret_cast<const char*>(
                g_wpack_hi + (size_t)phase * 256 * PACK_STRIDE);
            const char* lsrc = reinterpret_cast<const char*>(
                g_wpack_lo + (size_t)phase * 256 * PACK_STRIDE);
            #pragma unroll
            for (int i = 0; i < PACK_BYTES / 16 / GEMM_THREADS; i++) {   // 10
                int c = (i * GEMM_THREADS + tid) * 16;
                cp_async16(smem_u32 + SMEM_BH_OFF + c, hsrc + c, 16);
                cp_async16(smem_u32 + SMEM_BL_OFF + c, lsrc + c, 16);
            }
        }
        cp_async_commit_wait();
        __syncthreads();

        // ---- 8 k-steps of m16n8k8, 3 passes fused per k-step
        #pragma unroll
        for (int ks = 0; ks < KP / 8; ks++) {
            int kk = ks * 8;

            // A fragment: fp32 LDS then hi/lo tf32 split in registers
            float ar[4];
            ar[0] = xr[(g)     * XSTR + kk + t];
            ar[1] = xr[(g + 8) * XSTR + kk + t];
            ar[2] = xr[(g)     * XSTR + kk + t + 4];
            ar[3] = xr[(g + 8) * XSTR + kk + t + 4];
            uint32_t ah[4], al[4];
            #pragma unroll
            for (int i = 0; i < 4; i++) {
                ah[i] = tf32_rna(ar[i]);
                al[i] = tf32_rna(ar[i] - __uint_as_float(ah[i]));
            }

            // B fragments: this lane's packed row, 8x LDS.128 total
            uint32_t rowoff = (uint32_t)((ks * 32 + lane) * PACK_STRIDE) * 4;
            const uint4* bh4 = reinterpret_cast<const uint4*>(smem + SMEM_BH_OFF + rowoff);
            const uint4* bl4 = reinterpret_cast<const uint4*>(smem + SMEM_BL_OFF + rowoff);
            uint32_t bhw[16], blw[16];
            #pragma unroll
            for (int i = 0; i < 4; i++) {
                *reinterpret_cast<uint4*>(&bhw[i * 4]) = bh4[i];
                *reinterpret_cast<uint4*>(&blw[i * 4]) = bl4[i];
            }

            #pragma unroll
            for (int nt = 0; nt < 8; nt++) {
                uint32_t bh0 = bhw[2 * nt], bh1 = bhw[2 * nt + 1];
                uint32_t bl0 = blw[2 * nt], bl1 = blw[2 * nt + 1];
                mma_tf32(acc[nt], ah, bh0, bh1);   // xh*wh
                mma_tf32(acc[nt], ah, bl0, bl1);   // xh*wl
                mma_tf32(acc[nt], al, bh0, bh1);   // xl*wh
            }
        }
    }

    // ---- epilogue: c0,c1 -> (row g, cols 2t,2t+1); c2,c3 -> (row g+8)
    int row0 = bb + warp * 16 + g;
    int row1 = row0 + 8;
    #pragma unroll
    for (int nt = 0; nt < 8; nt++) {
        int col = nt * 8 + 2 * t;
        if (row0 < N_NODES)
            *reinterpret_cast<float2*>(g_hidden + (size_t)row0 * OUT_DIM + col)
                = make_float2(acc[nt][0], acc[nt][1]);
        if (row1 < N_NODES)
            *reinterpret_cast<float2*>(g_hidden + (size_t)row1 * OUT_DIM + col)
                = make_float2(acc[nt][2], acc[nt][3]);
    }
}

// ---------------------------------------------------------------------------
// Kernel 2: bucket fill (R10 verbatim)
// ---------------------------------------------------------------------------
__global__ void fill_kernel(const int* __restrict__ edge_row,
                            const int* __restrict__ edge_col,
                            const float* __restrict__ edge_val) {
    int i = blockIdx.x * blockDim.x + threadIdx.x;
    if (i >= N_EDGES / 4) return;

    int4   r4 = reinterpret_cast<const int4*>(edge_row)[i];
    int4   c4 = reinterpret_cast<const int4*>(edge_col)[i];
    float4 v4 = reinterpret_cast<const float4*>(edge_val)[i];

    int p;
    p = atomicAdd(&g_pos[r4.x], 1);
    if (p < CAP) g_edge[r4.x * CAP + p] = make_int2(c4.x, __float_as_int(v4.x));
    p = atomicAdd(&g_pos[r4.y], 1);
    if (p < CAP) g_edge[r4.y * CAP + p] = make_int2(c4.y, __float_as_int(v4.y));
    p = atomicAdd(&g_pos[r4.z], 1);
    if (p < CAP) g_edge[r4.z * CAP + p] = make_int2(c4.z, __float_as_int(v4.z));
    p = atomicAdd(&g_pos[r4.w], 1);
    if (p < CAP) g_edge[r4.w * CAP + p] = make_int2(c4.w, __float_as_int(v4.w));
}

// ---------------------------------------------------------------------------
// Kernel 3: fused accumulate + bias + relu (R10 verbatim)
// ---------------------------------------------------------------------------
__global__ void __launch_bounds__(256)
accum_kernel(float* __restrict__ out, const float* __restrict__ b) {
    int node = (blockIdx.x * blockDim.x + threadIdx.x) >> 5;
    int lane = threadIdx.x & 31;
    if (node >= N_NODES) return;

    int deg = g_pos[node];
    deg = deg < CAP ? deg : CAP;
    int off = node * CAP;

    float accx = 0.f, accy = 0.f;
    const float* hbase = g_hidden + lane * 2;

    int base = 0;
    int full = deg & ~31;
    for (; base < full; base += 32) {
        int2 ev = g_edge[off + base + lane];
        #pragma unroll
        for (int j = 0; j < 32; j++) {
            int   col = __shfl_sync(0xffffffffu, ev.x, j);
            float val = __int_as_float(__shfl_sync(0xffffffffu, ev.y, j));
            float2 hv = *reinterpret_cast<const float2*>(hbase + (size_t)col * OUT_DIM);
            accx = fmaf(val, hv.x, accx);
            accy = fmaf(val, hv.y, accy);
        }
    }
    int rem = deg - base;
    if (rem > 0) {
        int2 ev = (lane < rem) ? g_edge[off + base + lane] : make_int2(0, 0);
        for (int j = 0; j < rem; j++) {
            int   col = __shfl_sync(0xffffffffu, ev.x, j);
            float val = __int_as_float(__shfl_sync(0xffffffffu, ev.y, j));
            float2 hv = *reinterpret_cast<const float2*>(hbase + (size_t)col * OUT_DIM);
            accx = fmaf(val, hv.x, accx);
            accy = fmaf(val, hv.y, accy);
        }
    }

    float2 bv = reinterpret_cast<const float2*>(b)[lane];
    accx = fmaxf(accx + bv.x, 0.f);
    accy = fmaxf(accy + bv.y, 0.f);
    *reinterpret_cast<float2*>(out + (size_t)node * OUT_DIM + lane * 2)
        = make_float2(accx, accy);
}

// ---------------------------------------------------------------------------
extern "C" void kernel_launch(void* const* d_in, const int* in_sizes, int n_in,
                              void* d_out, int out_size) {
    const float* x        = (const float*)d_in[0];
    const int*   edge_row = (const int*)  d_in[1];
    const int*   edge_col = (const int*)  d_in[2];
    const float* edge_val = (const float*)d_in[3];
    const float* w        = (const float*)d_in[4];
    const float* b        = (const float*)d_in[5];
    float* out = (float*)d_out;

    cudaFuncSetAttribute(gemm_kernel,
                         cudaFuncAttributeMaxDynamicSharedMemorySize,
                         GEMM_SMEM_BYTES);

    pack_kernel<<<2, 256>>>(w);
    gemm_kernel<<<GEMM_GRID, GEMM_THREADS, GEMM_SMEM_BYTES>>>(x);  // + zero g_pos
    fill_kernel<<<(N_EDGES / 4 + 255) / 256, 256>>>(edge_row, edge_col, edge_val);
    accum_kernel<<<(N_NODES * 32 + 255) / 256, 256>>>(out, b);
}